// round 2
// baseline (speedup 1.0000x reference)
#include <cuda_runtime.h>
#include <math_constants.h>

// PCEN: [B=32, T=4096, F=256] fp32.
//   ema_t = w*x_t + (1-w)*ema_{t-1},  ema_{-1} = x_0
//   out   = (x * (EPS+ema)^(-g) + bias)^(1/r) - bias^(1/r)
//   then global min/max normalize to [-1, 1].
//
// Chunked parallel scan over T: 32 chunks of L=128 per (b,f) chain.

#define EPSC 1e-6f
#define BB   32
#define TT   4096
#define FF   256
#define LL   128
#define NCHUNK (TT / LL)        // 32
#define NCHAIN (BB * FF)        // 8192
#define NTHREAD (NCHAIN * NCHUNK) // 262144

// Scratch (device globals — no allocations allowed).
__device__ float    g_S[NTHREAD];   // chunk partial sums, layout [(b,c,f)] = tid
__device__ float    g_A[NTHREAD];   // chunk carry-in values, same layout
__device__ unsigned g_minmax[2];    // [0]=min key, [1]=max key (ordered-uint encoding)

// Monotone float <-> uint mapping (works for negatives).
__device__ __forceinline__ unsigned f2key(float f) {
    unsigned u = __float_as_uint(f);
    return (u & 0x80000000u) ? ~u : (u | 0x80000000u);
}
__device__ __forceinline__ float key2f(unsigned k) {
    return __uint_as_float((k & 0x80000000u) ? (k & 0x7FFFFFFFu) : ~k);
}

// ---------------------------------------------------------------------------
// K1: per-chunk local scan with zero carry-in. S_c = local ema at chunk end.
// tid layout: f = tid&255 (coalesced), c = (tid>>8)&31, b = tid>>13.
// ---------------------------------------------------------------------------
__global__ void __launch_bounds__(256) k1_chunk_scan(
    const float* __restrict__ x, const float* __restrict__ smooth)
{
    int tid = blockIdx.x * blockDim.x + threadIdx.x;
    int f = tid & (FF - 1);
    int c = (tid >> 8) & (NCHUNK - 1);
    int b = tid >> 13;

    float w   = fminf(fmaxf(smooth[0], 0.0f), 1.0f);
    float omw = 1.0f - w;

    const float* p = x + ((size_t)(b * TT + c * LL)) * FF + f;

    float a = 0.0f;
    #pragma unroll 8
    for (int i = 0; i < LL; i++) {
        a = fmaf(omw, a, w * p[(size_t)i * FF]);
    }
    g_S[tid] = a;
}

// ---------------------------------------------------------------------------
// K2: per-chain sequential combine of 32 chunk carries. Also inits minmax.
// One thread per chain (8192 threads). A_0 = ema_{-1} = x[b,0,f].
// ---------------------------------------------------------------------------
__global__ void __launch_bounds__(256) k2_combine(
    const float* __restrict__ x, const float* __restrict__ smooth)
{
    int tid = blockIdx.x * blockDim.x + threadIdx.x;
    if (tid == 0) {
        g_minmax[0] = 0xFFFFFFFFu;  // min key init (= +inf)
        g_minmax[1] = 0x00000000u;  // max key init (= -inf)
    }
    if (tid >= NCHAIN) return;

    int b = tid >> 8;
    int f = tid & (FF - 1);

    float w   = fminf(fmaxf(smooth[0], 0.0f), 1.0f);
    float omw = 1.0f - w;
    // D = omw^L exactly via 7 squarings (L = 128 = 2^7)
    float D = omw;
    #pragma unroll
    for (int i = 0; i < 7; i++) D *= D;

    float A = x[(size_t)b * TT * FF + f];  // ema_{-1} = x[b, 0, f]
    int base = (b * NCHUNK) * FF + f;
    #pragma unroll
    for (int c = 0; c < NCHUNK; c++) {
        g_A[base + c * FF] = A;
        A = g_S[base + c * FF] + D * A;
    }
}

// ---------------------------------------------------------------------------
// K3: re-scan each chunk with correct carry-in, apply PCEN nonlinearity,
// write output, reduce min/max (warp shuffle -> smem -> 2 atomics/block).
// ---------------------------------------------------------------------------
__global__ void __launch_bounds__(256) k3_pcen(
    const float* __restrict__ x, float* __restrict__ out,
    const float* __restrict__ gain, const float* __restrict__ bias,
    const float* __restrict__ root, const float* __restrict__ smooth)
{
    int tid = blockIdx.x * blockDim.x + threadIdx.x;
    int f = tid & (FF - 1);
    int c = (tid >> 8) & (NCHUNK - 1);
    int b = tid >> 13;

    float w   = fminf(fmaxf(smooth[0], 0.0f), 1.0f);
    float omw = 1.0f - w;
    float g   = fminf(gain[0], 1.0f);
    float r   = fmaxf(root[0], 1.0f);
    float oor = 1.0f / r;
    float bs  = bias[0];
    float bpow = __powf(bs, oor);

    size_t off = ((size_t)(b * TT + c * LL)) * FF + f;
    const float* p = x + off;
    float*       q = out + off;

    float a  = g_A[tid];
    float mn = CUDART_INF_F, mx = -CUDART_INF_F;

    #pragma unroll 4
    for (int i = 0; i < LL; i++) {
        float xv = p[(size_t)i * FF];
        a = fmaf(omw, a, w * xv);                       // ema
        float rden = __powf(EPSC + a, -g);              // (eps+ema)^(-g): lg2+ex2
        float v = __powf(fmaf(xv, rden, bs), oor) - bpow;
        q[(size_t)i * FF] = v;
        mn = fminf(mn, v);
        mx = fmaxf(mx, v);
    }

    // warp reduce
    #pragma unroll
    for (int o = 16; o; o >>= 1) {
        mn = fminf(mn, __shfl_xor_sync(0xFFFFFFFFu, mn, o));
        mx = fmaxf(mx, __shfl_xor_sync(0xFFFFFFFFu, mx, o));
    }
    __shared__ float smn[8], smx[8];
    int wid = threadIdx.x >> 5, lane = threadIdx.x & 31;
    if (lane == 0) { smn[wid] = mn; smx[wid] = mx; }
    __syncthreads();
    if (threadIdx.x == 0) {
        float bmn = smn[0], bmx = smx[0];
        #pragma unroll
        for (int i = 1; i < 8; i++) {
            bmn = fminf(bmn, smn[i]);
            bmx = fmaxf(bmx, smx[i]);
        }
        atomicMin(&g_minmax[0], f2key(bmn));
        atomicMax(&g_minmax[1], f2key(bmx));
    }
}

// ---------------------------------------------------------------------------
// K4: global min/max normalize, float4 vectorized.
// ---------------------------------------------------------------------------
__global__ void __launch_bounds__(256) k4_normalize(float* __restrict__ out, int n4)
{
    int i = blockIdx.x * blockDim.x + threadIdx.x;
    if (i >= n4) return;
    float mn = key2f(g_minmax[0]);
    float mx = key2f(g_minmax[1]);
    float sc = 2.0f / (mx - mn);
    float4 v = reinterpret_cast<float4*>(out)[i];
    v.x = fmaf(v.x - mn, sc, -1.0f);
    v.y = fmaf(v.y - mn, sc, -1.0f);
    v.z = fmaf(v.z - mn, sc, -1.0f);
    v.w = fmaf(v.w - mn, sc, -1.0f);
    reinterpret_cast<float4*>(out)[i] = v;
}

extern "C" void kernel_launch(void* const* d_in, const int* in_sizes, int n_in,
                              void* d_out, int out_size)
{
    const float* x      = (const float*)d_in[0];
    const float* gain   = (const float*)d_in[1];
    const float* bias   = (const float*)d_in[2];
    const float* root   = (const float*)d_in[3];
    const float* smooth = (const float*)d_in[4];
    float* out = (float*)d_out;

    k1_chunk_scan<<<NTHREAD / 256, 256>>>(x, smooth);
    k2_combine<<<NCHAIN / 256, 256>>>(x, smooth);
    k3_pcen<<<NTHREAD / 256, 256>>>(x, out, gain, bias, root, smooth);
    int n4 = (BB * TT * FF) / 4;
    k4_normalize<<<(n4 + 255) / 256, 256>>>(out, n4);
}

// round 3
// speedup vs baseline: 1.0743x; 1.0743x over previous
#include <cuda_runtime.h>
#include <math_constants.h>

// PCEN: [B=32, T=4096, F=256] fp32.
//   ema_t = w*x_t + (1-w)*ema_{t-1},  ema_{-1} = x_0
//   v     = (x*(EPS+ema)^(-g) + bias)^(1/r) - bias^(1/r)
//   out   = 2*(v - min v)/(max v - min v) - 1   (global min/max)
//
// Chunked scan (32 chunks of L=128) + monotonicity trick:
// v is monotone in u = x*(EPS+ema)^(-g), so min/max are reduced over u
// (2 MUFU/elem) and the unnormalized v is never materialized in memory.
// Traffic: 3x read of x + 1x write of out = 536 MB (vs 670 MB before).

#define EPSC 1e-6f
#define BB   32
#define TT   4096
#define FF   256
#define LL   128
#define NCHUNK (TT / LL)          // 32
#define NCHAIN (BB * FF)          // 8192
#define NTHREAD (NCHAIN * NCHUNK) // 262144

__device__ float    g_S[NTHREAD];   // chunk partial EMA sums, tid = (b,c,f)
__device__ float    g_A[NTHREAD];   // chunk carry-in values, same layout
__device__ unsigned g_minmax[2];    // [0]=min key of u, [1]=max key of u

// Monotone float <-> uint mapping (handles sign).
__device__ __forceinline__ unsigned f2key(float f) {
    unsigned u = __float_as_uint(f);
    return (u & 0x80000000u) ? ~u : (u | 0x80000000u);
}
__device__ __forceinline__ float key2f(unsigned k) {
    return __uint_as_float((k & 0x80000000u) ? (k & 0x7FFFFFFFu) : ~k);
}

// ---------------------------------------------------------------------------
// K1: per-chunk local scan with zero carry-in -> g_S.
// tid: f = tid&255 (coalesced), c = (tid>>8)&31, b = tid>>13.
// ---------------------------------------------------------------------------
__global__ void __launch_bounds__(256) k1_chunk_scan(
    const float* __restrict__ x, const float* __restrict__ smooth)
{
    int tid = blockIdx.x * blockDim.x + threadIdx.x;
    int f = tid & (FF - 1);
    int c = (tid >> 8) & (NCHUNK - 1);
    int b = tid >> 13;

    float w   = fminf(fmaxf(smooth[0], 0.0f), 1.0f);
    float omw = 1.0f - w;

    const float* p = x + ((size_t)(b * TT + c * LL)) * FF + f;

    float a = 0.0f;
    #pragma unroll 8
    for (int i = 0; i < LL; i++) {
        a = fmaf(omw, a, w * p[(size_t)i * FF]);
    }
    g_S[tid] = a;
}

// ---------------------------------------------------------------------------
// K2: per-chain sequential combine of 32 chunk carries -> g_A. Inits minmax.
// ---------------------------------------------------------------------------
__global__ void __launch_bounds__(256) k2_combine(
    const float* __restrict__ x, const float* __restrict__ smooth)
{
    int tid = blockIdx.x * blockDim.x + threadIdx.x;
    if (tid == 0) {
        g_minmax[0] = 0xFFFFFFFFu;  // min key init (= +inf)
        g_minmax[1] = 0x00000000u;  // max key init (= -inf)
    }
    if (tid >= NCHAIN) return;

    int b = tid >> 8;
    int f = tid & (FF - 1);

    float w   = fminf(fmaxf(smooth[0], 0.0f), 1.0f);
    float omw = 1.0f - w;
    float D = omw;                 // omw^128 via 7 squarings
    #pragma unroll
    for (int i = 0; i < 7; i++) D *= D;

    float A = x[(size_t)b * TT * FF + f];  // ema_{-1} = x[b,0,f]
    int base = (b * NCHUNK) * FF + f;
    #pragma unroll
    for (int c = 0; c < NCHUNK; c++) {
        g_A[base + c * FF] = A;
        A = g_S[base + c * FF] + D * A;
    }
}

// ---------------------------------------------------------------------------
// K3: rescan with carry, reduce global min/max of u = x*(EPS+ema)^(-g).
// No output write. 2 MUFU/elem.
// ---------------------------------------------------------------------------
__global__ void __launch_bounds__(256) k3_minmax(
    const float* __restrict__ x,
    const float* __restrict__ gain, const float* __restrict__ smooth)
{
    int tid = blockIdx.x * blockDim.x + threadIdx.x;
    int f = tid & (FF - 1);
    int c = (tid >> 8) & (NCHUNK - 1);
    int b = tid >> 13;

    float w   = fminf(fmaxf(smooth[0], 0.0f), 1.0f);
    float omw = 1.0f - w;
    float g   = fminf(gain[0], 1.0f);

    const float* p = x + ((size_t)(b * TT + c * LL)) * FF + f;

    float a  = g_A[tid];
    float mn = CUDART_INF_F, mx = -CUDART_INF_F;

    #pragma unroll 4
    for (int i = 0; i < LL; i++) {
        float xv = p[(size_t)i * FF];
        a = fmaf(omw, a, w * xv);
        float u = xv * __powf(EPSC + a, -g);
        mn = fminf(mn, u);
        mx = fmaxf(mx, u);
    }

    #pragma unroll
    for (int o = 16; o; o >>= 1) {
        mn = fminf(mn, __shfl_xor_sync(0xFFFFFFFFu, mn, o));
        mx = fmaxf(mx, __shfl_xor_sync(0xFFFFFFFFu, mx, o));
    }
    __shared__ float smn[8], smx[8];
    int wid = threadIdx.x >> 5, lane = threadIdx.x & 31;
    if (lane == 0) { smn[wid] = mn; smx[wid] = mx; }
    __syncthreads();
    if (threadIdx.x == 0) {
        float bmn = smn[0], bmx = smx[0];
        #pragma unroll
        for (int i = 1; i < 8; i++) {
            bmn = fminf(bmn, smn[i]);
            bmx = fmaxf(bmx, smx[i]);
        }
        atomicMin(&g_minmax[0], f2key(bmn));
        atomicMax(&g_minmax[1], f2key(bmx));
    }
}

// ---------------------------------------------------------------------------
// K4: rescan again, compute v' = (u+bias)^(1/r), normalize, write.
// bias^(1/r) cancels: out = (v' - v'min)*2/(v'max - v'min) - 1.
// v'min/v'max computed from u-keys with the SAME instruction sequence as the
// in-loop v', so the extreme elements map bit-exactly to -1/+1.
// ---------------------------------------------------------------------------
__global__ void __launch_bounds__(256) k4_output(
    const float* __restrict__ x, float* __restrict__ out,
    const float* __restrict__ gain, const float* __restrict__ bias,
    const float* __restrict__ root, const float* __restrict__ smooth)
{
    int tid = blockIdx.x * blockDim.x + threadIdx.x;
    int f = tid & (FF - 1);
    int c = (tid >> 8) & (NCHUNK - 1);
    int b = tid >> 13;

    float w   = fminf(fmaxf(smooth[0], 0.0f), 1.0f);
    float omw = 1.0f - w;
    float g   = fminf(gain[0], 1.0f);
    float r   = fmaxf(root[0], 1.0f);
    float oor = 1.0f / r;
    float bs  = bias[0];

    float vmn = __powf(key2f(g_minmax[0]) + bs, oor);
    float vmx = __powf(key2f(g_minmax[1]) + bs, oor);
    float sc  = 2.0f / (vmx - vmn);

    size_t off = ((size_t)(b * TT + c * LL)) * FF + f;
    const float* p = x + off;
    float*       q = out + off;

    float a = g_A[tid];

    #pragma unroll 4
    for (int i = 0; i < LL; i++) {
        float xv = p[(size_t)i * FF];
        a = fmaf(omw, a, w * xv);
        float u  = xv * __powf(EPSC + a, -g);
        float vp = __powf(u + bs, oor);
        q[(size_t)i * FF] = fmaf(vp - vmn, sc, -1.0f);
    }
}

extern "C" void kernel_launch(void* const* d_in, const int* in_sizes, int n_in,
                              void* d_out, int out_size)
{
    const float* x      = (const float*)d_in[0];
    const float* gain   = (const float*)d_in[1];
    const float* bias   = (const float*)d_in[2];
    const float* root   = (const float*)d_in[3];
    const float* smooth = (const float*)d_in[4];
    float* out = (float*)d_out;

    k1_chunk_scan<<<NTHREAD / 256, 256>>>(x, smooth);
    k2_combine<<<NCHAIN / 256, 256>>>(x, smooth);
    k3_minmax<<<NTHREAD / 256, 256>>>(x, gain, smooth);
    k4_output<<<NTHREAD / 256, 256>>>(x, out, gain, bias, root, smooth);
}